// round 3
// baseline (speedup 1.0000x reference)
#include <cuda_runtime.h>
#include <cuda_bf16.h>
#include <math.h>

#define CN 1024
#define HN 512
#define VN 32000
#define BN 16
#define TN 256
#define SPW 8
#define NCHUNK 15
#define CLEN 17   // 15*17 = 255 step matrices

// ------------------------- scratch (static device memory; no allocs) -------
__device__ __nv_bfloat16 g_tmpb[3 * CN * HN];  // relu(layer1) per chain, bf16
__device__ __nv_bfloat16 g_htb[CN * HN];       // trans residual out (bf16)
__device__ __nv_bfloat16 g_hpb[CN * HN];       // term residual out (bf16)
__device__ float g_sl[CN];
__device__ float g_startlp[CN];
__device__ float g_trans[CN * CN];
__device__ float g_pair[VN * SPW];             // pair logits -> emission handled via denom
__device__ unsigned g_maxk[CN];
__device__ float g_sumb[CN];
__device__ float g_denom[CN];
__device__ float g_pot[BN * 255 * 64];         // step matrices M_t (obs folded), [b][t-1][j*8+i]
__device__ float g_alpha0[BN * SPW];
__device__ float g_chunk[BN * NCHUNK * 64];    // chunk products

// monotonic float<->uint encoding for atomicMax on floats
__device__ __forceinline__ unsigned enc_f(float f) {
    int i = __float_as_int(f);
    return (unsigned)(i ^ ((i >> 31) | 0x80000000));
}
__device__ __forceinline__ float dec_f(unsigned u) {
    int i = (u & 0x80000000u) ? (int)(u ^ 0x80000000u) : ~(int)u;
    return __int_as_float(i);
}

// ---------------------------------------------------------------------------
// bf16 tensor-core GEMM core (see R2). Optional fused "head" epilogue:
// if headw != nullptr, instead of storing, accumulate row-dot partials with
// headw and atomicAdd into g_sl[row].
// ---------------------------------------------------------------------------
__device__ __forceinline__ void mma16816(float* d, const unsigned* a, const unsigned* b) {
    asm volatile(
        "mma.sync.aligned.m16n8k16.row.col.f32.bf16.bf16.f32 "
        "{%0,%1,%2,%3}, {%4,%5,%6,%7}, {%8,%9}, {%0,%1,%2,%3};\n"
        : "+f"(d[0]), "+f"(d[1]), "+f"(d[2]), "+f"(d[3])
        : "r"(a[0]), "r"(a[1]), "r"(a[2]), "r"(a[3]), "r"(b[0]), "r"(b[1]));
}

#define SSTRIDE 40  // bf16 elems per smem row (80B) -> conflict-free frag loads

template <bool ABF>
__device__ __forceinline__ void gemm_core(
    const float* __restrict__ Af, const __nv_bfloat16* __restrict__ Ab,
    const float* __restrict__ W, const float* __restrict__ bias,
    const float* __restrict__ res, float* __restrict__ outF,
    __nv_bfloat16* __restrict__ outB, const float* __restrict__ headw,
    int N, int K, int relu)
{
    __shared__ __nv_bfloat16 sA[64 * SSTRIDE];
    __shared__ __nv_bfloat16 sB[64 * SSTRIDE];

    const int t = threadIdx.x;
    const int lane = t & 31, warp = t >> 5;
    const int wm = warp >> 1, wn = warp & 1;
    const int row0 = blockIdx.y * 64, col0 = blockIdx.x * 64;
    const int lr = lane >> 2, lc = lane & 3;

    float acc[2][4][4];
#pragma unroll
    for (int mt = 0; mt < 2; mt++)
#pragma unroll
        for (int nt = 0; nt < 4; nt++)
#pragma unroll
            for (int q = 0; q < 4; q++) acc[mt][nt][q] = 0.f;

    float4 pa[4];
    uint2 pab[4];
    float4 pw[4];

#pragma unroll
    for (int i = 0; i < 4; i++) {
        int id = i * 128 + t, r = id >> 3, c4 = id & 7;
        if (ABF)
            pab[i] = *(const uint2*)(Ab + (size_t)(row0 + r) * K + c4 * 4);
        else
            pa[i] = *(const float4*)(Af + (size_t)(row0 + r) * K + c4 * 4);
        pw[i] = *(const float4*)(W + (size_t)(col0 + r) * K + c4 * 4);
    }

    const int NT = K / 32;
    for (int kt = 0; kt < NT; kt++) {
#pragma unroll
        for (int i = 0; i < 4; i++) {
            int id = i * 128 + t, r = id >> 3, c4 = id & 7;
            __nv_bfloat16* da = &sA[r * SSTRIDE + c4 * 4];
            if (ABF) {
                *(unsigned*)da = pab[i].x;
                *(unsigned*)(da + 2) = pab[i].y;
            } else {
                *(__nv_bfloat162*)da = __float22bfloat162_rn(make_float2(pa[i].x, pa[i].y));
                *(__nv_bfloat162*)(da + 2) = __float22bfloat162_rn(make_float2(pa[i].z, pa[i].w));
            }
            __nv_bfloat16* dw = &sB[r * SSTRIDE + c4 * 4];
            *(__nv_bfloat162*)dw = __float22bfloat162_rn(make_float2(pw[i].x, pw[i].y));
            *(__nv_bfloat162*)(dw + 2) = __float22bfloat162_rn(make_float2(pw[i].z, pw[i].w));
        }
        __syncthreads();

        int kn = (kt + 1) * 32;
        if (kn < K) {
#pragma unroll
            for (int i = 0; i < 4; i++) {
                int id = i * 128 + t, r = id >> 3, c4 = id & 7;
                if (ABF)
                    pab[i] = *(const uint2*)(Ab + (size_t)(row0 + r) * K + kn + c4 * 4);
                else
                    pa[i] = *(const float4*)(Af + (size_t)(row0 + r) * K + kn + c4 * 4);
                pw[i] = *(const float4*)(W + (size_t)(col0 + r) * K + kn + c4 * 4);
            }
        }

#pragma unroll
        for (int kk = 0; kk < 2; kk++) {
            unsigned af[2][4], bfr[4][2];
            int kb = kk * 16 + lc * 2;
#pragma unroll
            for (int mt = 0; mt < 2; mt++) {
                const __nv_bfloat16* p = &sA[(wm * 32 + mt * 16 + lr) * SSTRIDE + kb];
                af[mt][0] = *(const unsigned*)p;
                af[mt][1] = *(const unsigned*)(p + 8 * SSTRIDE);
                af[mt][2] = *(const unsigned*)(p + 8);
                af[mt][3] = *(const unsigned*)(p + 8 * SSTRIDE + 8);
            }
#pragma unroll
            for (int nt = 0; nt < 4; nt++) {
                const __nv_bfloat16* p = &sB[(wn * 32 + nt * 8 + lr) * SSTRIDE + kb];
                bfr[nt][0] = *(const unsigned*)p;
                bfr[nt][1] = *(const unsigned*)(p + 8);
            }
#pragma unroll
            for (int mt = 0; mt < 2; mt++)
#pragma unroll
                for (int nt = 0; nt < 4; nt++) mma16816(acc[mt][nt], af[mt], bfr[nt]);
        }
        __syncthreads();
    }

    float part[2][2] = {{0.f, 0.f}, {0.f, 0.f}};
#pragma unroll
    for (int mt = 0; mt < 2; mt++)
#pragma unroll
        for (int nt = 0; nt < 4; nt++) {
            int gr = row0 + wm * 32 + mt * 16 + lr;
            int gc = col0 + wn * 32 + nt * 8 + lc * 2;
            float2 b2 = make_float2(0.f, 0.f);
            if (bias) b2 = *(const float2*)(bias + gc);
#pragma unroll
            for (int h = 0; h < 2; h++) {
                int r_ = gr + h * 8;
                float v0 = acc[mt][nt][h * 2 + 0] + b2.x;
                float v1 = acc[mt][nt][h * 2 + 1] + b2.y;
                if (relu) { v0 = fmaxf(v0, 0.f); v1 = fmaxf(v1, 0.f); }
                if (res) {
                    float2 r2 = *(const float2*)(res + (size_t)r_ * N + gc);
                    v0 += r2.x; v1 += r2.y;
                }
                if (headw) {
                    float2 wv = *(const float2*)(headw + gc);
                    part[mt][h] = fmaf(v0, wv.x, fmaf(v1, wv.y, part[mt][h]));
                }
                if (outF) *(float2*)(outF + (size_t)r_ * N + gc) = make_float2(v0, v1);
                if (outB)
                    *(__nv_bfloat162*)(outB + (size_t)r_ * N + gc) =
                        __float22bfloat162_rn(make_float2(v0, v1));
            }
        }
    if (headw) {
        // reduce over the 4 lanes (lc) that share each row, then atomic
#pragma unroll
        for (int mt = 0; mt < 2; mt++)
#pragma unroll
            for (int h = 0; h < 2; h++) {
                float p = part[mt][h];
                p += __shfl_xor_sync(0xffffffffu, p, 1);
                p += __shfl_xor_sync(0xffffffffu, p, 2);
                if (lc == 0) {
                    int r_ = row0 + wm * 32 + mt * 16 + lr + h * 8;
                    atomicAdd(&g_sl[r_], p);
                }
            }
    }
}

// layer 1 (batched over z=3 chains)
__global__ __launch_bounds__(128) void gemm_l1_k(
    const float* A0, const float* A1, const float* A2,
    const float* W0, const float* W1, const float* W2,
    const float* B0, const float* B1, const float* B2)
{
    int z = blockIdx.z;
    const float* A = z == 0 ? A0 : (z == 1 ? A1 : A2);
    const float* W = z == 0 ? W0 : (z == 1 ? W1 : W2);
    const float* B = z == 0 ? B0 : (z == 1 ? B1 : B2);
    gemm_core<false>(A, nullptr, W, B, nullptr, nullptr,
                     g_tmpb + (size_t)z * CN * HN, nullptr, HN, HN, 1);
}

// layer 2 (batched). z0: head-fused (no store). z1 -> g_htb. z2 -> g_hpb.
__global__ __launch_bounds__(128) void gemm_l2_k(
    const float* W0, const float* W1, const float* W2,
    const float* B0, const float* B1, const float* B2,
    const float* R0, const float* R1, const float* R2,
    const float* ow)
{
    int z = blockIdx.z;
    const float* W = z == 0 ? W0 : (z == 1 ? W1 : W2);
    const float* B = z == 0 ? B0 : (z == 1 ? B1 : B2);
    const float* R = z == 0 ? R0 : (z == 1 ? R1 : R2);
    __nv_bfloat16* oB = z == 0 ? nullptr : (z == 1 ? g_htb : g_hpb);
    const float* hw = z == 0 ? ow : nullptr;
    gemm_core<true>(nullptr, g_tmpb + (size_t)z * CN * HN, W, B, R, nullptr, oB, hw,
                    HN, HN, 1);
}

// trans projection: g_trans = g_htb @ proj_w^T  (1024x1024x512), A in bf16
__global__ __launch_bounds__(128) void gemm_proj_k(const float* W)
{
    gemm_core<true>(nullptr, g_htb, W, nullptr, nullptr, g_trans, nullptr, nullptr,
                    CN, HN, 0);
}

// log_softmax over 1024 start logits (g_sl already holds head dots + bias)
__global__ __launch_bounds__(1024) void lsm_start_k()
{
    __shared__ float red[32];
    __shared__ float bc;
    int t = threadIdx.x;
    float v = g_sl[t];
    float m = v;
#pragma unroll
    for (int o = 16; o; o >>= 1) m = fmaxf(m, __shfl_xor_sync(0xffffffffu, m, o));
    if ((t & 31) == 0) red[t >> 5] = m;
    __syncthreads();
    if (t < 32) {
        float x = red[t];
#pragma unroll
        for (int o = 16; o; o >>= 1) x = fmaxf(x, __shfl_xor_sync(0xffffffffu, x, o));
        if (t == 0) bc = x;
    }
    __syncthreads();
    m = bc;
    float e = __expf(v - m);
    float s = e;
#pragma unroll
    for (int o = 16; o; o >>= 1) s += __shfl_xor_sync(0xffffffffu, s, o);
    __syncthreads();
    if ((t & 31) == 0) red[t >> 5] = s;
    __syncthreads();
    if (t < 32) {
        float x = red[t];
#pragma unroll
        for (int o = 16; o; o >>= 1) x += __shfl_xor_sync(0xffffffffu, x, o);
        if (t == 0) bc = x;
    }
    __syncthreads();
    g_startlp[t] = v - m - __logf(bc);
}

// per-row log_softmax of g_trans (1024x1024)
__global__ __launch_bounds__(256) void lsm_rows_k()
{
    __shared__ float red[8];
    __shared__ float bc;
    int row = blockIdx.x, t = threadIdx.x;
    float4* p4 = (float4*)(g_trans + (size_t)row * CN);
    float4 v = p4[t];
    float m = fmaxf(fmaxf(v.x, v.y), fmaxf(v.z, v.w));
#pragma unroll
    for (int o = 16; o; o >>= 1) m = fmaxf(m, __shfl_xor_sync(0xffffffffu, m, o));
    if ((t & 31) == 0) red[t >> 5] = m;
    __syncthreads();
    if (t < 8) {
        float x = red[t];
#pragma unroll
        for (int o = 4; o; o >>= 1) x = fmaxf(x, __shfl_xor_sync(0xffu, x, o));
        if (t == 0) bc = x;
    }
    __syncthreads();
    m = bc;
    float e = __expf(v.x - m) + __expf(v.y - m) + __expf(v.z - m) + __expf(v.w - m);
#pragma unroll
    for (int o = 16; o; o >>= 1) e += __shfl_xor_sync(0xffffffffu, e, o);
    __syncthreads();
    if ((t & 31) == 0) red[t >> 5] = e;
    __syncthreads();
    if (t < 8) {
        float x = red[t];
#pragma unroll
        for (int o = 4; o; o >>= 1) x += __shfl_xor_sync(0xffu, x, o);
        if (t == 0) bc = x;
    }
    __syncthreads();
    float lz = m + __logf(bc);
    p4[t] = make_float4(v.x - lz, v.y - lz, v.z - lz, v.w - lz);
}

// ---------------------------------------------------------------------------
// term sparse stage
// ---------------------------------------------------------------------------
__global__ void init_k(const float* __restrict__ ob)
{
    int i = blockIdx.x * 256 + threadIdx.x;
    if (i < CN) {
        g_maxk[i] = 0u;         // key 0 == -inf
        g_sumb[i] = 0.f;
        g_sl[i] = ob[0];        // head bias; GEMM epilogue atomicAdds the dot
    }
}

// one block per word: dot(hpb[c] (bf16), term_ow[v]) + ob[v] for its 8 states
__global__ __launch_bounds__(256) void term_pair_k(
    const float* __restrict__ tow, const float* __restrict__ tob,
    const int* __restrict__ w2s)
{
    __shared__ float ws[HN];
    __shared__ int cs[SPW];
    int v = blockIdx.x, tid = threadIdx.x;
    for (int i = tid; i < HN / 4; i += 256)
        ((float4*)ws)[i] = ((const float4*)(tow + (size_t)v * HN))[i];
    if (tid < SPW) cs[tid] = w2s[v * SPW + tid];
    __syncthreads();
    int warp = tid >> 5, lane = tid & 31;
    int c = cs[warp];
    const __nv_bfloat162* h2 = (const __nv_bfloat162*)(g_hpb + (size_t)c * HN);
    const float2* w2 = (const float2*)ws;
    float s = 0.f;
#pragma unroll
    for (int i = lane; i < HN / 2; i += 32) {
        __nv_bfloat162 h = h2[i];
        float2 w = w2[i];
        s = fmaf(__low2float(h), w.x, s);
        s = fmaf(__high2float(h), w.y, s);
    }
#pragma unroll
    for (int o = 16; o; o >>= 1) s += __shfl_xor_sync(0xffffffffu, s, o);
    if (lane == 0) {
        float logit = s + tob[v];
        g_pair[v * SPW + warp] = logit;
        bool dup = false;
        for (int k2 = 0; k2 < warp; k2++) if (cs[k2] == c) dup = true;
        if (!dup) atomicMax(&g_maxk[c], enc_f(logit));
    }
}

__global__ void term_sum_k(const int* __restrict__ w2s)
{
    int idx = blockIdx.x * 256 + threadIdx.x;
    if (idx >= VN * SPW) return;
    int v = idx >> 3, k = idx & 7;
    int c = w2s[idx];
    for (int k2 = 0; k2 < k; k2++) if (w2s[(v << 3) + k2] == c) return;
    atomicAdd(&g_sumb[c], __expf(g_pair[idx] - dec_f(g_maxk[c])));
}

__global__ void denom_k()
{
    int c = blockIdx.x * 256 + threadIdx.x;
    if (c < CN) g_denom[c] = dec_f(g_maxk[c]) + __logf(g_sumb[c]);
}

// ---------------------------------------------------------------------------
// parallel scan, phase 0: build step matrices M_t[j,i] (t=1..255, obs folded)
// grid (256, BN), 64 threads. Block t==0 builds alpha0 instead.
// ---------------------------------------------------------------------------
__global__ __launch_bounds__(64) void gather_k(
    const int* __restrict__ text, const int* __restrict__ w2s)
{
    int t = blockIdx.x, b = blockIdx.y, tid = threadIdx.x;
    if (t == 0) {
        if (tid < SPW) {
            int w0 = text[b * TN];
            int c0 = w2s[w0 * SPW + tid];
            g_alpha0[b * SPW + tid] =
                g_startlp[c0] + g_pair[w0 * SPW + tid] - g_denom[c0];
        }
        return;
    }
    int j = tid >> 3, i = tid & 7;
    int wp = text[b * TN + t - 1];
    int wc = text[b * TN + t];
    int ci = w2s[wp * SPW + i];
    int cj = w2s[wc * SPW + j];
    float m = g_trans[(size_t)ci * CN + cj] + g_pair[wc * SPW + j] - g_denom[cj];
    g_pot[((size_t)b * 255 + (t - 1)) * 64 + tid] = m;
}

// phase 1: fold each chunk of 17 step matrices into one 8x8 log-matrix.
// grid (NCHUNK, BN), 64 threads. P <- M_s (x) P  (lse-matmul), s ascending.
__global__ __launch_bounds__(64) void chunk_k()
{
    __shared__ float bufA[64], bufB[64];
    int c = blockIdx.x, b = blockIdx.y, tid = threadIdx.x;
    int j = tid >> 3, i = tid & 7;
    const float* base = g_pot + ((size_t)b * 255 + c * CLEN) * 64;
    float* cur = bufA;
    float* nxt = bufB;
    cur[tid] = base[tid];
    __syncthreads();
#pragma unroll 1
    for (int s = 1; s < CLEN; s++) {
        const float* Mrow = base + s * 64 + (j << 3);
        float v0 = Mrow[0] + cur[0 * 8 + i];
        float v1 = Mrow[1] + cur[1 * 8 + i];
        float v2 = Mrow[2] + cur[2 * 8 + i];
        float v3 = Mrow[3] + cur[3 * 8 + i];
        float v4 = Mrow[4] + cur[4 * 8 + i];
        float v5 = Mrow[5] + cur[5 * 8 + i];
        float v6 = Mrow[6] + cur[6 * 8 + i];
        float v7 = Mrow[7] + cur[7 * 8 + i];
        float m = fmaxf(fmaxf(fmaxf(v0, v1), fmaxf(v2, v3)),
                        fmaxf(fmaxf(v4, v5), fmaxf(v6, v7)));
        float sum = ((__expf(v0 - m) + __expf(v1 - m)) + (__expf(v2 - m) + __expf(v3 - m))) +
                    ((__expf(v4 - m) + __expf(v5 - m)) + (__expf(v6 - m) + __expf(v7 - m)));
        nxt[tid] = m + __logf(sum);
        __syncthreads();
        float* tmpp = cur; cur = nxt; nxt = tmpp;
        __syncthreads();
    }
    g_chunk[((size_t)b * NCHUNK + c) * 64 + tid] = cur[tid];
}

// phase 2: per batch, alpha0 through 15 chunk matrices; sum evidences.
// single block, 512 threads (warp w = batch w, lanes 0..7 active).
__global__ __launch_bounds__(512) void scanfin_k(float* __restrict__ out)
{
    __shared__ float ev[BN];
    int w = threadIdx.x >> 5, lane = threadIdx.x & 31;
    if (lane < 8) {
        int b = w;
        float an = g_alpha0[b * SPW + lane];
        float a[8];
#pragma unroll
        for (int i = 0; i < 8; i++) a[i] = __shfl_sync(0xFFu, an, i);
        for (int c = 0; c < NCHUNK; c++) {
            const float4* p4 =
                (const float4*)(g_chunk + ((size_t)b * NCHUNK + c) * 64 + (lane << 3));
            float4 pA = p4[0], pB = p4[1];
            float v0 = pA.x + a[0], v1 = pA.y + a[1], v2 = pA.z + a[2], v3 = pA.w + a[3];
            float v4 = pB.x + a[4], v5 = pB.y + a[5], v6 = pB.z + a[6], v7 = pB.w + a[7];
            float m = fmaxf(fmaxf(fmaxf(v0, v1), fmaxf(v2, v3)),
                            fmaxf(fmaxf(v4, v5), fmaxf(v6, v7)));
            float s = ((__expf(v0 - m) + __expf(v1 - m)) + (__expf(v2 - m) + __expf(v3 - m))) +
                      ((__expf(v4 - m) + __expf(v5 - m)) + (__expf(v6 - m) + __expf(v7 - m)));
            an = m + __logf(s);
#pragma unroll
            for (int i = 0; i < 8; i++) a[i] = __shfl_sync(0xFFu, an, i);
        }
        if (lane == 0) {
            float m = a[0];
#pragma unroll
            for (int i = 1; i < 8; i++) m = fmaxf(m, a[i]);
            float s = 0.f;
#pragma unroll
            for (int i = 0; i < 8; i++) s += __expf(a[i] - m);
            ev[b] = m + __logf(s);
        }
    }
    __syncthreads();
    if (threadIdx.x == 0) {
        float s = 0.f;
#pragma unroll
        for (int b = 0; b < BN; b++) s += ev[b];
        out[0] = s;
    }
}

// ---------------------------------------------------------------------------
extern "C" void kernel_launch(void* const* d_in, const int* in_sizes, int n_in,
                              void* d_out, int out_size)
{
    const float* start_emb = (const float*)d_in[0];
    const float* start_l1w = (const float*)d_in[1];
    const float* start_l1b = (const float*)d_in[2];
    const float* start_l2w = (const float*)d_in[3];
    const float* start_l2b = (const float*)d_in[4];
    const float* start_ow  = (const float*)d_in[5];
    const float* start_ob  = (const float*)d_in[6];
    const float* state_emb = (const float*)d_in[7];
    const float* trans_l1w = (const float*)d_in[8];
    const float* trans_l1b = (const float*)d_in[9];
    const float* trans_l2w = (const float*)d_in[10];
    const float* trans_l2b = (const float*)d_in[11];
    const float* proj_w    = (const float*)d_in[12];
    const float* pret_emb  = (const float*)d_in[13];
    const float* term_l1w  = (const float*)d_in[14];
    const float* term_l1b  = (const float*)d_in[15];
    const float* term_l2w  = (const float*)d_in[16];
    const float* term_l2b  = (const float*)d_in[17];
    const float* term_ow   = (const float*)d_in[18];
    const float* term_ob   = (const float*)d_in[19];
    const int*   text      = (const int*)d_in[20];
    const int*   w2s       = (const int*)d_in[21];
    float* out = (float*)d_out;

    dim3 blk(256);

    init_k<<<4, blk>>>(start_ob);

    // residual MLPs on tensor cores (3 chains batched in z); start head fused
    gemm_l1_k<<<dim3(HN / 64, CN / 64, 3), 128>>>(
        start_emb, state_emb, pret_emb,
        start_l1w, trans_l1w, term_l1w,
        start_l1b, trans_l1b, term_l1b);
    gemm_l2_k<<<dim3(HN / 64, CN / 64, 3), 128>>>(
        start_l2w, trans_l2w, term_l2w,
        start_l2b, trans_l2b, term_l2b,
        start_emb, state_emb, pret_emb,
        start_ow);

    lsm_start_k<<<1, 1024>>>();

    // transition matrix + row log_softmax
    gemm_proj_k<<<dim3(CN / 64, CN / 64, 1), 128>>>(proj_w);
    lsm_rows_k<<<CN, blk>>>();

    // emission (sparse)
    term_pair_k<<<VN, blk>>>(term_ow, term_ob, w2s);
    term_sum_k<<<(VN * SPW + 255) / 256, blk>>>(w2s);
    denom_k<<<(CN + 255) / 256, blk>>>();

    // parallel forward scan
    gather_k<<<dim3(TN, BN), 64>>>(text, w2s);
    chunk_k<<<dim3(NCHUNK, BN), 64>>>();
    scanfin_k<<<1, 512>>>(out);
}

// round 4
// speedup vs baseline: 1.6427x; 1.6427x over previous
#include <cuda_runtime.h>
#include <cuda_bf16.h>
#include <math.h>

#define CN 1024
#define HN 512
#define VN 32000
#define BN 16
#define TN 256
#define SPW 8
#define NCHUNK 15
#define CLEN 17   // 15*17 = 255 step matrices

// ------------------------- scratch (static device memory; no allocs) -------
__device__ __nv_bfloat16 g_tmpb[3 * CN * HN];  // relu(layer1) per chain, bf16
__device__ __nv_bfloat16 g_htb[CN * HN];       // trans residual out (bf16)
__device__ __nv_bfloat16 g_hpb[CN * HN];       // term residual out (bf16)
__device__ float g_sl[CN];                     // start logits (bias + fused head dots)
__device__ float g_startlp[CN];                // start log-probs
__device__ float g_trans[CN * CN];             // raw trans logits
__device__ float g_rowlz[CN];                  // per-row logZ of g_trans
__device__ float g_pair[VN * SPW];             // term pair logits
__device__ float g_sumb[CN];                   // sum exp(logit) per state
__device__ float g_chunk[BN * NCHUNK * 64];    // chunk products
__device__ float g_ev[BN];
__device__ unsigned g_cnt1;
__device__ unsigned g_cnt2;

// ---------------------------------------------------------------------------
// bf16 tensor-core GEMM core. Optional fused "head" epilogue: accumulate
// row-dot partials with headw and atomicAdd into g_sl[row].
// ---------------------------------------------------------------------------
__device__ __forceinline__ void mma16816(float* d, const unsigned* a, const unsigned* b) {
    asm volatile(
        "mma.sync.aligned.m16n8k16.row.col.f32.bf16.bf16.f32 "
        "{%0,%1,%2,%3}, {%4,%5,%6,%7}, {%8,%9}, {%0,%1,%2,%3};\n"
        : "+f"(d[0]), "+f"(d[1]), "+f"(d[2]), "+f"(d[3])
        : "r"(a[0]), "r"(a[1]), "r"(a[2]), "r"(a[3]), "r"(b[0]), "r"(b[1]));
}

#define SSTRIDE 40  // bf16 elems per smem row (80B) -> conflict-free frag loads

template <bool ABF>
__device__ __forceinline__ void gemm_core(
    const float* __restrict__ Af, const __nv_bfloat16* __restrict__ Ab,
    const float* __restrict__ W, const float* __restrict__ bias,
    const float* __restrict__ res, float* __restrict__ outF,
    __nv_bfloat16* __restrict__ outB, const float* __restrict__ headw,
    int N, int K, int relu)
{
    __shared__ __nv_bfloat16 sA[64 * SSTRIDE];
    __shared__ __nv_bfloat16 sB[64 * SSTRIDE];

    const int t = threadIdx.x;
    const int lane = t & 31, warp = t >> 5;
    const int wm = warp >> 1, wn = warp & 1;
    const int row0 = blockIdx.y * 64, col0 = blockIdx.x * 64;
    const int lr = lane >> 2, lc = lane & 3;

    float acc[2][4][4];
#pragma unroll
    for (int mt = 0; mt < 2; mt++)
#pragma unroll
        for (int nt = 0; nt < 4; nt++)
#pragma unroll
            for (int q = 0; q < 4; q++) acc[mt][nt][q] = 0.f;

    float4 pa[4];
    uint2 pab[4];
    float4 pw[4];

#pragma unroll
    for (int i = 0; i < 4; i++) {
        int id = i * 128 + t, r = id >> 3, c4 = id & 7;
        if (ABF)
            pab[i] = *(const uint2*)(Ab + (size_t)(row0 + r) * K + c4 * 4);
        else
            pa[i] = *(const float4*)(Af + (size_t)(row0 + r) * K + c4 * 4);
        pw[i] = *(const float4*)(W + (size_t)(col0 + r) * K + c4 * 4);
    }

    const int NT = K / 32;
    for (int kt = 0; kt < NT; kt++) {
#pragma unroll
        for (int i = 0; i < 4; i++) {
            int id = i * 128 + t, r = id >> 3, c4 = id & 7;
            __nv_bfloat16* da = &sA[r * SSTRIDE + c4 * 4];
            if (ABF) {
                *(unsigned*)da = pab[i].x;
                *(unsigned*)(da + 2) = pab[i].y;
            } else {
                *(__nv_bfloat162*)da = __float22bfloat162_rn(make_float2(pa[i].x, pa[i].y));
                *(__nv_bfloat162*)(da + 2) = __float22bfloat162_rn(make_float2(pa[i].z, pa[i].w));
            }
            __nv_bfloat16* dw = &sB[r * SSTRIDE + c4 * 4];
            *(__nv_bfloat162*)dw = __float22bfloat162_rn(make_float2(pw[i].x, pw[i].y));
            *(__nv_bfloat162*)(dw + 2) = __float22bfloat162_rn(make_float2(pw[i].z, pw[i].w));
        }
        __syncthreads();

        int kn = (kt + 1) * 32;
        if (kn < K) {
#pragma unroll
            for (int i = 0; i < 4; i++) {
                int id = i * 128 + t, r = id >> 3, c4 = id & 7;
                if (ABF)
                    pab[i] = *(const uint2*)(Ab + (size_t)(row0 + r) * K + kn + c4 * 4);
                else
                    pa[i] = *(const float4*)(Af + (size_t)(row0 + r) * K + kn + c4 * 4);
                pw[i] = *(const float4*)(W + (size_t)(col0 + r) * K + kn + c4 * 4);
            }
        }

#pragma unroll
        for (int kk = 0; kk < 2; kk++) {
            unsigned af[2][4], bfr[4][2];
            int kb = kk * 16 + lc * 2;
#pragma unroll
            for (int mt = 0; mt < 2; mt++) {
                const __nv_bfloat16* p = &sA[(wm * 32 + mt * 16 + lr) * SSTRIDE + kb];
                af[mt][0] = *(const unsigned*)p;
                af[mt][1] = *(const unsigned*)(p + 8 * SSTRIDE);
                af[mt][2] = *(const unsigned*)(p + 8);
                af[mt][3] = *(const unsigned*)(p + 8 * SSTRIDE + 8);
            }
#pragma unroll
            for (int nt = 0; nt < 4; nt++) {
                const __nv_bfloat16* p = &sB[(wn * 32 + nt * 8 + lr) * SSTRIDE + kb];
                bfr[nt][0] = *(const unsigned*)p;
                bfr[nt][1] = *(const unsigned*)(p + 8);
            }
#pragma unroll
            for (int mt = 0; mt < 2; mt++)
#pragma unroll
                for (int nt = 0; nt < 4; nt++) mma16816(acc[mt][nt], af[mt], bfr[nt]);
        }
        __syncthreads();
    }

    float part[2][2] = {{0.f, 0.f}, {0.f, 0.f}};
#pragma unroll
    for (int mt = 0; mt < 2; mt++)
#pragma unroll
        for (int nt = 0; nt < 4; nt++) {
            int gr = row0 + wm * 32 + mt * 16 + lr;
            int gc = col0 + wn * 32 + nt * 8 + lc * 2;
            float2 b2 = make_float2(0.f, 0.f);
            if (bias) b2 = *(const float2*)(bias + gc);
#pragma unroll
            for (int h = 0; h < 2; h++) {
                int r_ = gr + h * 8;
                float v0 = acc[mt][nt][h * 2 + 0] + b2.x;
                float v1 = acc[mt][nt][h * 2 + 1] + b2.y;
                if (relu) { v0 = fmaxf(v0, 0.f); v1 = fmaxf(v1, 0.f); }
                if (res) {
                    float2 r2 = *(const float2*)(res + (size_t)r_ * N + gc);
                    v0 += r2.x; v1 += r2.y;
                }
                if (headw) {
                    float2 wv = *(const float2*)(headw + gc);
                    part[mt][h] = fmaf(v0, wv.x, fmaf(v1, wv.y, part[mt][h]));
                }
                if (outF) *(float2*)(outF + (size_t)r_ * N + gc) = make_float2(v0, v1);
                if (outB)
                    *(__nv_bfloat162*)(outB + (size_t)r_ * N + gc) =
                        __float22bfloat162_rn(make_float2(v0, v1));
            }
        }
    if (headw) {
#pragma unroll
        for (int mt = 0; mt < 2; mt++)
#pragma unroll
            for (int h = 0; h < 2; h++) {
                float p = part[mt][h];
                p += __shfl_xor_sync(0xffffffffu, p, 1);
                p += __shfl_xor_sync(0xffffffffu, p, 2);
                if (lc == 0) {
                    int r_ = row0 + wm * 32 + mt * 16 + lr + h * 8;
                    atomicAdd(&g_sl[r_], p);
                }
            }
    }
}

// layer 1 (batched over z=3 chains). Block (0,0,0) also initializes scratch.
__global__ __launch_bounds__(128) void gemm_l1_k(
    const float* A0, const float* A1, const float* A2,
    const float* W0, const float* W1, const float* W2,
    const float* B0, const float* B1, const float* B2,
    const float* ob)
{
    int z = blockIdx.z;
    if (z == 0 && blockIdx.x == 0 && blockIdx.y == 0) {
        float ob0 = ob[0];
        for (int i = threadIdx.x; i < CN; i += 128) {
            g_sl[i] = ob0;
            g_sumb[i] = 0.f;
        }
        if (threadIdx.x == 0) { g_cnt1 = 0u; g_cnt2 = 0u; }
    }
    const float* A = z == 0 ? A0 : (z == 1 ? A1 : A2);
    const float* W = z == 0 ? W0 : (z == 1 ? W1 : W2);
    const float* B = z == 0 ? B0 : (z == 1 ? B1 : B2);
    gemm_core<false>(A, nullptr, W, B, nullptr, nullptr,
                     g_tmpb + (size_t)z * CN * HN, nullptr, HN, HN, 1);
}

// layer 2 (batched). z0: head-fused (no store). z1 -> g_htb. z2 -> g_hpb.
__global__ __launch_bounds__(128) void gemm_l2_k(
    const float* W0, const float* W1, const float* W2,
    const float* B0, const float* B1, const float* B2,
    const float* R0, const float* R1, const float* R2,
    const float* ow)
{
    int z = blockIdx.z;
    const float* W = z == 0 ? W0 : (z == 1 ? W1 : W2);
    const float* B = z == 0 ? B0 : (z == 1 ? B1 : B2);
    const float* R = z == 0 ? R0 : (z == 1 ? R1 : R2);
    __nv_bfloat16* oB = z == 0 ? nullptr : (z == 1 ? g_htb : g_hpb);
    const float* hw = z == 0 ? ow : nullptr;
    gemm_core<true>(nullptr, g_tmpb + (size_t)z * CN * HN, W, B, R, nullptr, oB, hw,
                    HN, HN, 1);
}

// trans projection: g_trans = g_htb @ proj_w^T  (1024x1024x512), A in bf16
__global__ __launch_bounds__(128) void gemm_proj_k(const float* W)
{
    gemm_core<true>(nullptr, g_htb, W, nullptr, nullptr, g_trans, nullptr, nullptr,
                    CN, HN, 0);
}

// ---------------------------------------------------------------------------
// row logsumexp of g_trans (blocks 0..CN-1 -> g_rowlz[row]);
// block CN: start log_softmax over g_sl -> g_startlp.
// ---------------------------------------------------------------------------
__global__ __launch_bounds__(256) void rowlse_k()
{
    __shared__ float red[8];
    __shared__ float bc;
    int row = blockIdx.x, t = threadIdx.x;
    const float* src = (row == CN) ? g_sl : (g_trans + (size_t)row * CN);
    float4 v = ((const float4*)src)[t];
    float m = fmaxf(fmaxf(v.x, v.y), fmaxf(v.z, v.w));
#pragma unroll
    for (int o = 16; o; o >>= 1) m = fmaxf(m, __shfl_xor_sync(0xffffffffu, m, o));
    if ((t & 31) == 0) red[t >> 5] = m;
    __syncthreads();
    if (t < 8) {
        float x = red[t];
#pragma unroll
        for (int o = 4; o; o >>= 1) x = fmaxf(x, __shfl_xor_sync(0xffu, x, o));
        if (t == 0) bc = x;
    }
    __syncthreads();
    m = bc;
    float e = __expf(v.x - m) + __expf(v.y - m) + __expf(v.z - m) + __expf(v.w - m);
#pragma unroll
    for (int o = 16; o; o >>= 1) e += __shfl_xor_sync(0xffffffffu, e, o);
    __syncthreads();
    if ((t & 31) == 0) red[t >> 5] = e;
    __syncthreads();
    if (t < 8) {
        float x = red[t];
#pragma unroll
        for (int o = 4; o; o >>= 1) x += __shfl_xor_sync(0xffu, x, o);
        if (t == 0) bc = x;
    }
    __syncthreads();
    float lz = m + __logf(bc);
    if (row == CN)
        ((float4*)g_startlp)[t] = make_float4(v.x - lz, v.y - lz, v.z - lz, v.w - lz);
    else if (t == 0)
        g_rowlz[row] = lz;
}

// ---------------------------------------------------------------------------
// term sparse stage: one block per word. Computes the 8 pair logits and
// accumulates exp(logit) into g_sumb[state] (dedup'd). No max pass needed:
// logits are O(1) so exp cannot overflow/underflow in fp32.
// ---------------------------------------------------------------------------
__global__ __launch_bounds__(256) void term_pair_k(
    const float* __restrict__ tow, const float* __restrict__ tob,
    const int* __restrict__ w2s)
{
    __shared__ float ws[HN];
    __shared__ int cs[SPW];
    int v = blockIdx.x, tid = threadIdx.x;
    for (int i = tid; i < HN / 4; i += 256)
        ((float4*)ws)[i] = ((const float4*)(tow + (size_t)v * HN))[i];
    if (tid < SPW) cs[tid] = w2s[v * SPW + tid];
    __syncthreads();
    int warp = tid >> 5, lane = tid & 31;
    int c = cs[warp];
    const uint4* h4 = (const uint4*)(g_hpb + (size_t)c * HN);  // 64 uint4 per row
    const float4* wsv = (const float4*)ws;
    float s = 0.f;
#pragma unroll
    for (int it = 0; it < 2; it++) {
        int idx = it * 32 + lane;
        uint4 q = h4[idx];
        float4 w0 = wsv[idx * 2], w1 = wsv[idx * 2 + 1];
        __nv_bfloat162 p0 = *(__nv_bfloat162*)&q.x;
        __nv_bfloat162 p1 = *(__nv_bfloat162*)&q.y;
        __nv_bfloat162 p2 = *(__nv_bfloat162*)&q.z;
        __nv_bfloat162 p3 = *(__nv_bfloat162*)&q.w;
        s = fmaf(__low2float(p0), w0.x, s);
        s = fmaf(__high2float(p0), w0.y, s);
        s = fmaf(__low2float(p1), w0.z, s);
        s = fmaf(__high2float(p1), w0.w, s);
        s = fmaf(__low2float(p2), w1.x, s);
        s = fmaf(__high2float(p2), w1.y, s);
        s = fmaf(__low2float(p3), w1.z, s);
        s = fmaf(__high2float(p3), w1.w, s);
    }
#pragma unroll
    for (int o = 16; o; o >>= 1) s += __shfl_xor_sync(0xffffffffu, s, o);
    if (lane == 0) {
        float logit = s + tob[v];
        g_pair[v * SPW + warp] = logit;
        bool dup = false;
        for (int k2 = 0; k2 < warp; k2++) if (cs[k2] == c) dup = true;
        if (!dup) atomicAdd(&g_sumb[c], __expf(logit));
    }
}

// ---------------------------------------------------------------------------
// fused parallel scan: grid (NCHUNK, BN), 64 threads.
// Each block gathers its 17 step matrices inline (trans raw + rowlz + obs)
// and folds them into one 8x8 log-matrix. Then a manual grid-sync; blocks
// (0,b) finish batch b; block (0,0) sums evidences into out[0].
// ---------------------------------------------------------------------------
__global__ __launch_bounds__(64) void scan_all_k(
    const int* __restrict__ text, const int* __restrict__ w2s,
    float* __restrict__ out)
{
    __shared__ int sw[CLEN + 1];
    __shared__ int sws[CLEN + 1][8];
    __shared__ float emi[CLEN + 1][8];   // valid s>=1
    __shared__ float rlz[CLEN + 1][8];
    __shared__ float bufA[64], bufB[64], sM[64];
    __shared__ float evs[BN];

    int c = blockIdx.x, b = blockIdx.y, tid = threadIdx.x;
    int base = b * TN + c * CLEN;

    if (tid < CLEN + 1) sw[tid] = text[base + tid];
    __syncthreads();
    for (int idx = tid; idx < (CLEN + 1) * 8; idx += 64) {
        int s = idx >> 3, j = idx & 7;
        int st = w2s[sw[s] * 8 + j];
        sws[s][j] = st;
        rlz[s][j] = g_rowlz[st];
        if (s >= 1) emi[s][j] = g_pair[sw[s] * 8 + j] - __logf(g_sumb[st]);
    }
    __syncthreads();

    int j = tid >> 3, i = tid & 7;
    float* cur = bufA;
    float* nxt = bufB;
    // step matrix s (0..16): M[j,i] = trans[sws[s][i], sws[s+1][j]] - rowlz(ci) + emi
    cur[tid] = g_trans[(size_t)sws[0][i] * CN + sws[1][j]] - rlz[0][i] + emi[1][j];
    float pend = g_trans[(size_t)sws[1][i] * CN + sws[2][j]] - rlz[1][i] + emi[2][j];
    __syncthreads();

    for (int s = 1; s < CLEN; s++) {
        sM[tid] = pend;
        if (s + 1 < CLEN)
            pend = g_trans[(size_t)sws[s + 1][i] * CN + sws[s + 2][j]]
                   - rlz[s + 1][i] + emi[s + 2][j];
        __syncthreads();
        const float* Mr = &sM[j << 3];
        float v0 = Mr[0] + cur[0 * 8 + i];
        float v1 = Mr[1] + cur[1 * 8 + i];
        float v2 = Mr[2] + cur[2 * 8 + i];
        float v3 = Mr[3] + cur[3 * 8 + i];
        float v4 = Mr[4] + cur[4 * 8 + i];
        float v5 = Mr[5] + cur[5 * 8 + i];
        float v6 = Mr[6] + cur[6 * 8 + i];
        float v7 = Mr[7] + cur[7 * 8 + i];
        float m = fmaxf(fmaxf(fmaxf(v0, v1), fmaxf(v2, v3)),
                        fmaxf(fmaxf(v4, v5), fmaxf(v6, v7)));
        float sum = ((__expf(v0 - m) + __expf(v1 - m)) + (__expf(v2 - m) + __expf(v3 - m))) +
                    ((__expf(v4 - m) + __expf(v5 - m)) + (__expf(v6 - m) + __expf(v7 - m)));
        nxt[tid] = m + __logf(sum);
        __syncthreads();
        float* tp = cur; cur = nxt; nxt = tp;
    }
    g_chunk[((size_t)b * NCHUNK + c) * 64 + tid] = cur[tid];
    __threadfence();
    __syncthreads();
    if (tid == 0) atomicAdd(&g_cnt1, 1u);
    if (c != 0) return;

    // ---- finisher for batch b ----
    if (tid == 0) {
        while (atomicAdd(&g_cnt1, 0u) < (unsigned)(NCHUNK * BN)) __nanosleep(64);
    }
    __syncthreads();
    __threadfence();

    if (tid < 8) {
        int c0 = sws[0][tid];  // states of first word (base offset 0 since c==0)
        float an = g_startlp[c0] + g_pair[sw[0] * 8 + tid] - __logf(g_sumb[c0]);
        float a[8];
#pragma unroll
        for (int q = 0; q < 8; q++) a[q] = __shfl_sync(0xFFu, an, q);
        for (int cc = 0; cc < NCHUNK; cc++) {
            const float4* p4 =
                (const float4*)(g_chunk + ((size_t)b * NCHUNK + cc) * 64 + (tid << 3));
            float4 pA = p4[0], pB = p4[1];
            float v0 = pA.x + a[0], v1 = pA.y + a[1], v2 = pA.z + a[2], v3 = pA.w + a[3];
            float v4 = pB.x + a[4], v5 = pB.y + a[5], v6 = pB.z + a[6], v7 = pB.w + a[7];
            float m = fmaxf(fmaxf(fmaxf(v0, v1), fmaxf(v2, v3)),
                            fmaxf(fmaxf(v4, v5), fmaxf(v6, v7)));
            float s = ((__expf(v0 - m) + __expf(v1 - m)) + (__expf(v2 - m) + __expf(v3 - m))) +
                      ((__expf(v4 - m) + __expf(v5 - m)) + (__expf(v6 - m) + __expf(v7 - m)));
            an = m + __logf(s);
#pragma unroll
            for (int q = 0; q < 8; q++) a[q] = __shfl_sync(0xFFu, an, q);
        }
        if (tid == 0) {
            float m = a[0];
#pragma unroll
            for (int q = 1; q < 8; q++) m = fmaxf(m, a[q]);
            float s = 0.f;
#pragma unroll
            for (int q = 0; q < 8; q++) s += __expf(a[q] - m);
            g_ev[b] = m + __logf(s);
            __threadfence();
            atomicAdd(&g_cnt2, 1u);
        }
    }
    if (b != 0) return;

    if (tid == 0) {
        while (atomicAdd(&g_cnt2, 0u) < (unsigned)BN) __nanosleep(64);
        __threadfence();
        float s = 0.f;
#pragma unroll
        for (int q = 0; q < BN; q++) s += g_ev[q];
        out[0] = s;
    }
}

// ---------------------------------------------------------------------------
extern "C" void kernel_launch(void* const* d_in, const int* in_sizes, int n_in,
                              void* d_out, int out_size)
{
    const float* start_emb = (const float*)d_in[0];
    const float* start_l1w = (const float*)d_in[1];
    const float* start_l1b = (const float*)d_in[2];
    const float* start_l2w = (const float*)d_in[3];
    const float* start_l2b = (const float*)d_in[4];
    const float* start_ow  = (const float*)d_in[5];
    const float* start_ob  = (const float*)d_in[6];
    const float* state_emb = (const float*)d_in[7];
    const float* trans_l1w = (const float*)d_in[8];
    const float* trans_l1b = (const float*)d_in[9];
    const float* trans_l2w = (const float*)d_in[10];
    const float* trans_l2b = (const float*)d_in[11];
    const float* proj_w    = (const float*)d_in[12];
    const float* pret_emb  = (const float*)d_in[13];
    const float* term_l1w  = (const float*)d_in[14];
    const float* term_l1b  = (const float*)d_in[15];
    const float* term_l2w  = (const float*)d_in[16];
    const float* term_l2b  = (const float*)d_in[17];
    const float* term_ow   = (const float*)d_in[18];
    const float* term_ob   = (const float*)d_in[19];
    const int*   text      = (const int*)d_in[20];
    const int*   w2s       = (const int*)d_in[21];
    float* out = (float*)d_out;

    // 1) layer-1 GEMMs (3 chains) + scratch init in block 0
    gemm_l1_k<<<dim3(HN / 64, CN / 64, 3), 128>>>(
        start_emb, state_emb, pret_emb,
        start_l1w, trans_l1w, term_l1w,
        start_l1b, trans_l1b, term_l1b,
        start_ob);
    // 2) layer-2 GEMMs (start head fused via atomics)
    gemm_l2_k<<<dim3(HN / 64, CN / 64, 3), 128>>>(
        start_l2w, trans_l2w, term_l2w,
        start_l2b, trans_l2b, term_l2b,
        start_emb, state_emb, pret_emb,
        start_ow);
    // 3) transition projection
    gemm_proj_k<<<dim3(CN / 64, CN / 64, 1), 128>>>(proj_w);
    // 4) row logsumexp of trans + start log_softmax (extra block)
    rowlse_k<<<CN + 1, 256>>>();
    // 5) sparse term logits + exp-sum per state
    term_pair_k<<<VN, 256>>>(term_ow, term_ob, w2s);
    // 6) fused parallel scan + final evidence
    scan_all_k<<<dim3(NCHUNK, BN), 64>>>(text, w2s, out);
}